// round 15
// baseline (speedup 1.0000x reference)
#include <cuda_runtime.h>
#include <cuda_bf16.h>
#include <cuda_fp16.h>
#include <cstdint>

#define N_NODES 50000
#define N_EDGES 800000
#define IN_DIM  256
#define H1      512
#define H2      128
#define M_PAD   50048   // multiple of 128

// -------------------- scratch --------------------
__device__ float g_deg [N_NODES];
__device__ float g_dinv[N_NODES];
__device__ int   g_counts[N_NODES];
__device__ int   g_rank[N_EDGES];
__device__ int   g_offs [N_NODES + 1];
__device__ unsigned long long g_pkt[256];
__device__ unsigned int g_ticket;
__device__ int2  g_edge[N_EDGES];                     // packed (src, w-bits)
__device__ __half g_xh  [(size_t)N_NODES * IN_DIM];
__device__ __half g_xw2h[(size_t)M_PAD * H2];
__device__ __nv_bfloat16 g_a1hi[(size_t)M_PAD * IN_DIM];
__device__ __nv_bfloat16 g_a1lo[(size_t)M_PAD * IN_DIM];
__device__ __nv_bfloat16 g_f1hi[(size_t)M_PAD * H1];
__device__ __nv_bfloat16 g_f1lo[(size_t)M_PAD * H1];
__device__ __nv_bfloat16 g_w1thi[(size_t)H1 * IN_DIM];
__device__ __nv_bfloat16 g_w1tlo[(size_t)H1 * IN_DIM];
__device__ __nv_bfloat16 g_w2thi[(size_t)H2 * H1];
__device__ __nv_bfloat16 g_w2tlo[(size_t)H2 * H1];

// -------------------- helpers --------------------
__device__ __forceinline__ void mma_bf16(float* c, const uint32_t* a, const uint32_t* b) {
    asm volatile(
        "mma.sync.aligned.m16n8k16.row.col.f32.bf16.bf16.f32 "
        "{%0,%1,%2,%3}, {%4,%5,%6,%7}, {%8,%9}, {%0,%1,%2,%3};"
        : "+f"(c[0]), "+f"(c[1]), "+f"(c[2]), "+f"(c[3])
        : "r"(a[0]), "r"(a[1]), "r"(a[2]), "r"(a[3]), "r"(b[0]), "r"(b[1]));
}

__device__ __forceinline__ void ldsm4(uint32_t& r0, uint32_t& r1, uint32_t& r2,
                                      uint32_t& r3, uint32_t a) {
    asm volatile("ldmatrix.sync.aligned.m8n8.x4.shared.b16 {%0,%1,%2,%3}, [%4];"
                 : "=r"(r0), "=r"(r1), "=r"(r2), "=r"(r3) : "r"(a));
}

__device__ __forceinline__ void cp16(uint32_t saddr, const void* g) {
    asm volatile("cp.async.cg.shared.global [%0], [%1], 16;" :: "r"(saddr), "l"(g));
}
#define CP_COMMIT() asm volatile("cp.async.commit_group;" ::: "memory")
#define CP_WAIT(n)  asm volatile("cp.async.wait_group %0;" :: "n"(n) : "memory")

__device__ __forceinline__ uint32_t smem_u32(const void* p) {
    uint32_t a;
    asm("{ .reg .u64 t; cvta.to.shared.u64 t, %1; cvt.u32.u64 %0, t; }" : "=r"(a) : "l"(p));
    return a;
}

__device__ __forceinline__ void split4(float4 v, uint2& hi, uint2& lo) {
    __nv_bfloat16 h0 = __float2bfloat16(v.x), h1 = __float2bfloat16(v.y);
    __nv_bfloat16 h2 = __float2bfloat16(v.z), h3 = __float2bfloat16(v.w);
    __nv_bfloat162 hp0; hp0.x = h0; hp0.y = h1;
    __nv_bfloat162 hp1; hp1.x = h2; hp1.y = h3;
    __nv_bfloat162 lp0, lp1;
    lp0.x = __float2bfloat16(v.x - __bfloat162float(h0));
    lp0.y = __float2bfloat16(v.y - __bfloat162float(h1));
    lp1.x = __float2bfloat16(v.z - __bfloat162float(h2));
    lp1.y = __float2bfloat16(v.w - __bfloat162float(h3));
    hi = make_uint2(*(uint32_t*)&hp0, *(uint32_t*)&hp1);
    lo = make_uint2(*(uint32_t*)&lp0, *(uint32_t*)&lp1);
}

__device__ __forceinline__ void facc8(float* a, float w, uint4 u) {
    __half2 h0 = *(__half2*)&u.x, h1 = *(__half2*)&u.y;
    __half2 h2 = *(__half2*)&u.z, h3 = *(__half2*)&u.w;
    float2 f;
    f = __half22float2(h0); a[0] = fmaf(w, f.x, a[0]); a[1] = fmaf(w, f.y, a[1]);
    f = __half22float2(h1); a[2] = fmaf(w, f.x, a[2]); a[3] = fmaf(w, f.y, a[3]);
    f = __half22float2(h2); a[4] = fmaf(w, f.x, a[4]); a[5] = fmaf(w, f.y, a[5]);
    f = __half22float2(h3); a[6] = fmaf(w, f.x, a[6]); a[7] = fmaf(w, f.y, a[7]);
}

__device__ __forceinline__ float4 fma4h(float4 a, float w, uint2 u) {
    __half2 h0 = *(__half2*)&u.x, h1 = *(__half2*)&u.y;
    float2 f0 = __half22float2(h0), f1 = __half22float2(h1);
    a.x = fmaf(w, f0.x, a.x); a.y = fmaf(w, f0.y, a.y);
    a.z = fmaf(w, f1.x, a.z); a.w = fmaf(w, f1.y, a.w);
    return a;
}

// -------------------- CSR build --------------------
__global__ void init_all(float* deg, int* counts, int n) {
    int i = blockIdx.x * blockDim.x + threadIdx.x;
    if (i < n) { deg[i] = 1.0f; counts[i] = 0; }
    if (i < 256) g_pkt[i] = 0ull;
    if (i == 0) g_ticket = 0u;
}

__global__ void edge_accum(const int* __restrict__ col, const float* __restrict__ ew,
                           float* deg, int* counts, int* __restrict__ rank, int E) {
    int e = blockIdx.x * blockDim.x + threadIdx.x;
    if (e < E) {
        int c = col[e];
        atomicAdd(&deg[c], ew[e]);
        rank[e] = atomicAdd(&counts[c], 1);
    }
}

// fused: dinv = rsqrt(deg) + single-pass exclusive scan (warp-parallel lookback)
__global__ __launch_bounds__(256)
void rsqrt_scan_lb(const float* __restrict__ deg, float* __restrict__ dinv,
                   const int* __restrict__ counts, int* __restrict__ offs,
                   int n, int nb) {
    __shared__ int sh[256];
    __shared__ int bid_s, exc_s;
    const int t = threadIdx.x;
    if (t == 0) bid_s = (int)atomicAdd(&g_ticket, 1u);
    __syncthreads();
    const int bid = bid_s;
    const int gid = bid * 256 + t;

    if (gid < n) {
        float d = deg[gid];
        dinv[gid] = d > 0.f ? rsqrtf(d) : 0.f;
    }

    int v = (gid < n) ? counts[gid] : 0;
    sh[t] = v;
    __syncthreads();
#pragma unroll
    for (int d = 1; d < 256; d <<= 1) {
        int u = (t >= d) ? sh[t - d] : 0;
        __syncthreads();
        sh[t] += u;
        __syncthreads();
    }
    const int total = sh[255];

    if (t < 32) {
        if (bid == 0) {
            if (t == 0) {
                atomicExch(&g_pkt[0], (2ull << 32) | (unsigned)total);
                exc_s = 0;
            }
        } else {
            if (t == 0) atomicExch(&g_pkt[bid], (1ull << 32) | (unsigned)total);
            int exc = 0;
            int base_j = bid - 1;
            while (true) {
                int idx = base_j - t;
                unsigned long long p = 0;
                if (idx >= 0) {
                    do { p = atomicAdd(&g_pkt[idx], 0ull); } while ((p >> 32) == 0);
                }
                unsigned fm = __ballot_sync(0xffffffffu, idx >= 0 && (p >> 32) == 2ull);
                int tpre = __ffs(fm) - 1;
                unsigned contrib = (idx >= 0 && (tpre < 0 || t <= tpre)) ? (unsigned)p : 0u;
#pragma unroll
                for (int o = 16; o; o >>= 1) contrib += __shfl_xor_sync(0xffffffffu, contrib, o);
                exc += (int)contrib;
                if (tpre >= 0) break;
                base_j -= 32;
            }
            if (t == 0) {
                atomicExch(&g_pkt[bid], (2ull << 32) | (unsigned)(exc + total));
                exc_s = exc;
            }
        }
    }
    __syncthreads();
    const int base = exc_s;
    if (gid < n) offs[gid] = base + sh[t] - v;
    if (bid == nb - 1 && t == 255) offs[n] = base + total;
}

__global__ void fill_csr(const int* __restrict__ row, const int* __restrict__ col,
                         const float* __restrict__ ew, const float* __restrict__ dinv,
                         const int* __restrict__ offs, const int* __restrict__ rank,
                         int2* __restrict__ edges, int E) {
    int e = blockIdx.x * blockDim.x + threadIdx.x;
    if (e >= E) return;
    int r = row[e], c = col[e];
    int pos = offs[c] + rank[e];
    float w = dinv[r] * ew[e] * dinv[c];
    edges[pos] = make_int2(r, __float_as_int(w));
}

// x -> fp16
__global__ void x2h(const float4* __restrict__ x, uint2* __restrict__ xh, long n4) {
    long i = (long)blockIdx.x * blockDim.x + threadIdx.x;
    if (i >= n4) return;
    float4 v = x[i];
    __half2 p0 = __floats2half2_rn(v.x, v.y);
    __half2 p1 = __floats2half2_rn(v.z, v.w);
    xh[i] = make_uint2(*(uint32_t*)&p0, *(uint32_t*)&p1);
}

// both weight transposes + splits in one launch
__global__ void decompW(const float* __restrict__ W1, const float* __restrict__ W2,
                        __nv_bfloat16* __restrict__ w1hi, __nv_bfloat16* __restrict__ w1lo,
                        __nv_bfloat16* __restrict__ w2hi, __nv_bfloat16* __restrict__ w2lo) {
    const int n1 = IN_DIM * H1;
    const int n2 = H1 * H2;
    int i = blockIdx.x * blockDim.x + threadIdx.x;
    if (i < n1) {
        int k = i / H1, n = i % H1;
        float v = W1[i];
        __nv_bfloat16 h = __float2bfloat16(v);
        w1hi[(size_t)n * IN_DIM + k] = h;
        w1lo[(size_t)n * IN_DIM + k] = __float2bfloat16(v - __bfloat162float(h));
    } else if (i < n1 + n2) {
        int j = i - n1;
        int k = j / H2, n = j % H2;
        float v = W2[j];
        __nv_bfloat16 h = __float2bfloat16(v);
        w2hi[(size_t)n * H1 + k] = h;
        w2lo[(size_t)n * H1 + k] = __float2bfloat16(v - __bfloat162float(h));
    }
}

// -------------------- gather aggregations (warp per destination) ------------
__global__ __launch_bounds__(256)
void gather1(const float4* __restrict__ x, const uint4* __restrict__ xh,
             const int2* __restrict__ edges, const int* __restrict__ offs,
             const float* __restrict__ dinv,
             uint4* __restrict__ hi, uint4* __restrict__ lo, int n_nodes) {
    int node = blockIdx.x * 8 + (threadIdx.x >> 5);
    if (node >= n_nodes) return;
    const int lane = threadIdx.x & 31;
    const int s = offs[node], e = offs[node + 1];
    const float dv = dinv[node];
    const float sl = dv * dv;

    float a[8];
    {
        const float4* xr = x + (size_t)node * 64 + lane * 2;
        float4 v0 = __ldg(xr), v1 = __ldg(xr + 1);
        a[0] = sl * v0.x; a[1] = sl * v0.y; a[2] = sl * v0.z; a[3] = sl * v0.w;
        a[4] = sl * v1.x; a[5] = sl * v1.y; a[6] = sl * v1.z; a[7] = sl * v1.w;
    }

    int k = s;
    for (; k + 4 <= e; k += 4) {
        int2 e0 = __ldg(edges + k),     e1 = __ldg(edges + k + 1);
        int2 e2 = __ldg(edges + k + 2), e3 = __ldg(edges + k + 3);
        uint4 u0 = __ldg(xh + (size_t)e0.x * 32 + lane);
        uint4 u1 = __ldg(xh + (size_t)e1.x * 32 + lane);
        uint4 u2 = __ldg(xh + (size_t)e2.x * 32 + lane);
        uint4 u3 = __ldg(xh + (size_t)e3.x * 32 + lane);
        facc8(a, __int_as_float(e0.y), u0);
        facc8(a, __int_as_float(e1.y), u1);
        facc8(a, __int_as_float(e2.y), u2);
        facc8(a, __int_as_float(e3.y), u3);
    }
    for (; k < e; k++) {
        int2 e0 = __ldg(edges + k);
        facc8(a, __int_as_float(e0.y), __ldg(xh + (size_t)e0.x * 32 + lane));
    }

    uint2 h0, l0, h1, l1;
    split4(make_float4(a[0], a[1], a[2], a[3]), h0, l0);
    split4(make_float4(a[4], a[5], a[6], a[7]), h1, l1);
    hi[(size_t)node * 32 + lane] = make_uint4(h0.x, h0.y, h1.x, h1.y);
    lo[(size_t)node * 32 + lane] = make_uint4(l0.x, l0.y, l1.x, l1.y);
}

__global__ __launch_bounds__(256)
void gather2(const uint2* __restrict__ xwh, const int2* __restrict__ edges,
             const int* __restrict__ offs, const float* __restrict__ dinv,
             const float* __restrict__ b2, const float* __restrict__ alpha,
             float4* __restrict__ out, int n_nodes) {
    int node = blockIdx.x * 8 + (threadIdx.x >> 5);
    if (node >= n_nodes) return;
    const int lane = threadIdx.x & 31;
    const int s = offs[node], e = offs[node + 1];
    const float dv = dinv[node];
    const float sl = dv * dv;

    float4 a = make_float4(0.f, 0.f, 0.f, 0.f);
    a = fma4h(a, sl, __ldg(xwh + (size_t)node * 32 + lane));

    int k = s;
    for (; k + 8 <= e; k += 8) {
        int2 e0 = __ldg(edges + k),     e1 = __ldg(edges + k + 1);
        int2 e2 = __ldg(edges + k + 2), e3 = __ldg(edges + k + 3);
        int2 e4 = __ldg(edges + k + 4), e5 = __ldg(edges + k + 5);
        int2 e6 = __ldg(edges + k + 6), e7 = __ldg(edges + k + 7);
        uint2 u0 = __ldg(xwh + (size_t)e0.x * 32 + lane);
        uint2 u1 = __ldg(xwh + (size_t)e1.x * 32 + lane);
        uint2 u2 = __ldg(xwh + (size_t)e2.x * 32 + lane);
        uint2 u3 = __ldg(xwh + (size_t)e3.x * 32 + lane);
        uint2 u4 = __ldg(xwh + (size_t)e4.x * 32 + lane);
        uint2 u5 = __ldg(xwh + (size_t)e5.x * 32 + lane);
        uint2 u6 = __ldg(xwh + (size_t)e6.x * 32 + lane);
        uint2 u7 = __ldg(xwh + (size_t)e7.x * 32 + lane);
        a = fma4h(a, __int_as_float(e0.y), u0); a = fma4h(a, __int_as_float(e1.y), u1);
        a = fma4h(a, __int_as_float(e2.y), u2); a = fma4h(a, __int_as_float(e3.y), u3);
        a = fma4h(a, __int_as_float(e4.y), u4); a = fma4h(a, __int_as_float(e5.y), u5);
        a = fma4h(a, __int_as_float(e6.y), u6); a = fma4h(a, __int_as_float(e7.y), u7);
    }
    for (; k < e; k++) {
        int2 e0 = __ldg(edges + k);
        a = fma4h(a, __int_as_float(e0.y), __ldg(xwh + (size_t)e0.x * 32 + lane));
    }

    float4 bb = __ldg((const float4*)b2 + lane);
    float al = __ldg(alpha);
    a.x += bb.x; a.y += bb.y; a.z += bb.z; a.w += bb.w;
    a.x = a.x >= 0.f ? a.x : al * a.x;
    a.y = a.y >= 0.f ? a.y : al * a.y;
    a.z = a.z >= 0.f ? a.z : al * a.z;
    a.w = a.w >= 0.f ? a.w : al * a.w;
    out[(size_t)node * 32 + lane] = a;
}

// ---------- bf16x3 GEMM: HMMA + ldmatrix + 3-stage cp.async pipeline ----------
// OUT_MODE 0: fp16 C0. OUT_MODE 1: bias+PReLU, emit bf16 hi(C0)/lo(C1).
#define SPAD 40

template <int OUT_MODE, int MI>
__global__ __launch_bounds__(256)
void gemm_mma2(const __nv_bfloat16* __restrict__ Ahi, const __nv_bfloat16* __restrict__ Alo,
               const __nv_bfloat16* __restrict__ Bhi, const __nv_bfloat16* __restrict__ Blo,
               void* C0, void* C1, int Nc, int K,
               const float* __restrict__ bias, const float* __restrict__ alpha) {
    constexpr int BM = 32 * MI;
    constexpr int A_TILE = BM * SPAD;
    constexpr int B_TILE = 128 * SPAD;
    constexpr int STAGE  = 2 * A_TILE + 2 * B_TILE;

    extern __shared__ __nv_bfloat16 sm[];
    const uint32_t sbase = smem_u32(sm);

    const int tid  = threadIdx.x;
    const int wid  = tid >> 5;
    const int lane = tid & 31;
    const int wm   = wid >> 2;
    const int wn   = wid & 3;
    const int m0   = blockIdx.y * BM;
    const int n0   = blockIdx.x * 128;
    const int r4   = lane >> 2;
    const int t2   = (lane & 3) * 2;

    float acc[MI][4][4];
#pragma unroll
    for (int i = 0; i < MI; i++)
#pragma unroll
        for (int j = 0; j < 4; j++)
#pragma unroll
            for (int q = 0; q < 4; q++) acc[i][j][q] = 0.f;

    const int ldr = tid >> 2;
    const int ldq = tid & 3;
    const __nv_bfloat16* gAh = Ahi + (size_t)(m0 + ldr) * K + ldq * 8;
    const __nv_bfloat16* gAl = Alo + (size_t)(m0 + ldr) * K + ldq * 8;
    const __nv_bfloat16* gBh = Bhi + (size_t)(n0 + ldr) * K + ldq * 8;
    const __nv_bfloat16* gBl = Blo + (size_t)(n0 + ldr) * K + ldq * 8;

    auto tile_load = [&](int kc, int b) {
#pragma unroll
        for (int h = 0; h < MI / 2; h++) {
            uint32_t sa = sbase + (uint32_t)((b * STAGE + (ldr + h * 64) * SPAD + ldq * 8) * 2);
            cp16(sa, gAh + kc + (size_t)h * 64 * K);
            sa = sbase + (uint32_t)((b * STAGE + A_TILE + (ldr + h * 64) * SPAD + ldq * 8) * 2);
            cp16(sa, gAl + kc + (size_t)h * 64 * K);
        }
#pragma unroll
        for (int h = 0; h < 2; h++) {
            uint32_t sa = sbase + (uint32_t)((b * STAGE + 2 * A_TILE +
                              (ldr + h * 64) * SPAD + ldq * 8) * 2);
            cp16(sa, gBh + kc + (size_t)h * 64 * K);
            sa = sbase + (uint32_t)((b * STAGE + 2 * A_TILE + B_TILE +
                              (ldr + h * 64) * SPAD + ldq * 8) * 2);
            cp16(sa, gBl + kc + (size_t)h * 64 * K);
        }
    };

    const int arow = wm * (MI * 16) + (lane & 15);
    const int aoff = (lane >> 4) * 8;
    const int brow = wn * 32 + (lane & 7) + ((lane >> 4) & 1) * 8;
    const int boff = ((lane >> 3) & 1) * 8;

    const int nch = K >> 5;   // >= 8
    tile_load(0, 0); CP_COMMIT();
    tile_load(32, 1); CP_COMMIT();

    for (int it = 0; it < nch; it++) {
        if (it + 2 < nch) {
            tile_load((it + 2) * 32, (it + 2) % 3);
            CP_COMMIT();
            CP_WAIT(2);
        } else if (it + 1 < nch) {
            CP_WAIT(1);
        } else {
            CP_WAIT(0);
        }
        __syncthreads();

        const int buf = it % 3;
        const uint32_t aH = sbase + (uint32_t)((buf * STAGE) * 2);
        const uint32_t aL = aH + (uint32_t)(A_TILE * 2);
        const uint32_t bH = aH + (uint32_t)(2 * A_TILE * 2);
        const uint32_t bL = bH + (uint32_t)(B_TILE * 2);

#pragma unroll
        for (int kk = 0; kk < 32; kk += 16) {
            uint32_t bh[4][2], bl[4][2];
#pragma unroll
            for (int jp = 0; jp < 2; jp++) {
                uint32_t ad = bH + (uint32_t)(((brow + jp * 16) * SPAD + kk + boff) * 2);
                ldsm4(bh[2*jp][0], bh[2*jp][1], bh[2*jp+1][0], bh[2*jp+1][1], ad);
                ad = bL + (uint32_t)(((brow + jp * 16) * SPAD + kk + boff) * 2);
                ldsm4(bl[2*jp][0], bl[2*jp][1], bl[2*jp+1][0], bl[2*jp+1][1], ad);
            }
#pragma unroll
            for (int i = 0; i < MI; i++) {
                uint32_t ah[4], al[4];
                uint32_t ad = aH + (uint32_t)(((arow + i * 16) * SPAD + kk + aoff) * 2);
                ldsm4(ah[0], ah[1], ah[2], ah[3], ad);
                ad = aL + (uint32_t)(((arow + i * 16) * SPAD + kk + aoff) * 2);
                ldsm4(al[0], al[1], al[2], al[3], ad);
#pragma unroll
                for (int j = 0; j < 4; j++) {
                    mma_bf16(acc[i][j], ah, bh[j]);
                    mma_bf16(acc[i][j], ah, bl[j]);
                    mma_bf16(acc[i][j], al, bh[j]);
                }
            }
        }
        __syncthreads();
    }

    const float al_ = (OUT_MODE == 1) ? alpha[0] : 0.f;
#pragma unroll
    for (int i = 0; i < MI; i++) {
#pragma unroll
        for (int j = 0; j < 4; j++) {
            const int gm = m0 + wm * (MI * 16) + i * 16 + r4;
            const int gn = n0 + wn * 32 + j * 8 + t2;
            if (OUT_MODE == 0) {
                __half2 p0 = __floats2half2_rn(acc[i][j][0], acc[i][j][1]);
                __half2 p1 = __floats2half2_rn(acc[i][j][2], acc[i][j][3]);
                ((uint32_t*)C0)[((size_t)gm * Nc + gn) >> 1]       = *(uint32_t*)&p0;
                ((uint32_t*)C0)[((size_t)(gm + 8) * Nc + gn) >> 1] = *(uint32_t*)&p1;
            } else {
                const float bb0 = bias[gn], bb1 = bias[gn + 1];
#pragma unroll
                for (int h = 0; h < 2; h++) {
                    float v0 = acc[i][j][h * 2 + 0] + bb0;
                    float v1 = acc[i][j][h * 2 + 1] + bb1;
                    v0 = v0 >= 0.f ? v0 : al_ * v0;
                    v1 = v1 >= 0.f ? v1 : al_ * v1;
                    __nv_bfloat16 h0 = __float2bfloat16(v0), h1 = __float2bfloat16(v1);
                    __nv_bfloat162 hp; hp.x = h0; hp.y = h1;
                    __nv_bfloat162 lp;
                    lp.x = __float2bfloat16(v0 - __bfloat162float(h0));
                    lp.y = __float2bfloat16(v1 - __bfloat162float(h1));
                    const size_t go = ((size_t)(gm + h * 8) * Nc + gn) >> 1;
                    ((uint32_t*)C0)[go] = *(uint32_t*)&hp;
                    ((uint32_t*)C1)[go] = *(uint32_t*)&lp;
                }
            }
        }
    }
}

#define SMEM_MI4 (3 * (2 * 128 * SPAD + 2 * 128 * SPAD) * 2)   // 122880 B
#define SMEM_MI2 (3 * (2 * 64 * SPAD + 2 * 128 * SPAD) * 2)    // 92160 B

// -------------------- launch --------------------
extern "C" void kernel_launch(void* const* d_in, const int* in_sizes, int n_in,
                              void* d_out, int out_size) {
    const float* x     = (const float*)d_in[0];
    const float* ew    = (const float*)d_in[1];
    const float* W1    = (const float*)d_in[2];
    const float* b1    = (const float*)d_in[3];
    const float* W2    = (const float*)d_in[4];
    const float* b2    = (const float*)d_in[5];
    const float* alpha = (const float*)d_in[6];
    const int*   eidx  = (const int*)  d_in[7];

    const int E = in_sizes[1];
    const int N = in_sizes[0] / IN_DIM;
    const int* row = eidx;
    const int* col = eidx + E;
    float* out = (float*)d_out;

    float *deg, *dinv;
    int *counts, *rank, *offs;
    int2* edges;
    __half *xh, *xw2h;
    __nv_bfloat16 *a1hi, *a1lo, *f1hi, *f1lo, *w1thi, *w1tlo, *w2thi, *w2tlo;
    cudaGetSymbolAddress((void**)&deg,    g_deg);
    cudaGetSymbolAddress((void**)&dinv,   g_dinv);
    cudaGetSymbolAddress((void**)&counts, g_counts);
    cudaGetSymbolAddress((void**)&rank,   g_rank);
    cudaGetSymbolAddress((void**)&offs,   g_offs);
    cudaGetSymbolAddress((void**)&edges,  g_edge);
    cudaGetSymbolAddress((void**)&xh,     g_xh);
    cudaGetSymbolAddress((void**)&xw2h,   g_xw2h);
    cudaGetSymbolAddress((void**)&a1hi,   g_a1hi);
    cudaGetSymbolAddress((void**)&a1lo,   g_a1lo);
    cudaGetSymbolAddress((void**)&f1hi,   g_f1hi);
    cudaGetSymbolAddress((void**)&f1lo,   g_f1lo);
    cudaGetSymbolAddress((void**)&w1thi,  g_w1thi);
    cudaGetSymbolAddress((void**)&w1tlo,  g_w1tlo);
    cudaGetSymbolAddress((void**)&w2thi,  g_w2thi);
    cudaGetSymbolAddress((void**)&w2tlo,  g_w2tlo);

    static bool once = false;
    static cudaStream_t s1, s2;
    static cudaEvent_t evRoot, evX, evW;
    if (!once) {
        cudaFuncSetAttribute((const void*)gemm_mma2<1, 4>, cudaFuncAttributeMaxDynamicSharedMemorySize, SMEM_MI4);
        cudaFuncSetAttribute((const void*)gemm_mma2<0, 2>, cudaFuncAttributeMaxDynamicSharedMemorySize, SMEM_MI2);
        cudaStreamCreateWithFlags(&s1, cudaStreamNonBlocking);
        cudaStreamCreateWithFlags(&s2, cudaStreamNonBlocking);
        cudaEventCreateWithFlags(&evRoot, cudaEventDisableTiming);
        cudaEventCreateWithFlags(&evX,    cudaEventDisableTiming);
        cudaEventCreateWithFlags(&evW,    cudaEventDisableTiming);
        once = true;
    }

    const int NB = (N + 255) / 256;   // 196 (<= 256 lookback slots)

    // fork: prep work on side streams
    cudaEventRecord(evRoot, 0);
    cudaStreamWaitEvent(s1, evRoot, 0);
    cudaStreamWaitEvent(s2, evRoot, 0);
    x2h<<<(int)(((long)N * 64 + 255) / 256), 256, 0, s1>>>((const float4*)x, (uint2*)xh, (long)N * 64);
    cudaEventRecord(evX, s1);
    decompW<<<(IN_DIM * H1 + H1 * H2 + 255) / 256, 256, 0, s2>>>(W1, W2, w1thi, w1tlo, w2thi, w2tlo);
    cudaEventRecord(evW, s2);

    // main stream: CSR build
    init_all<<<NB, 256>>>(deg, counts, N);
    edge_accum<<<(E + 255) / 256, 256>>>(col, ew, deg, counts, rank, E);
    rsqrt_scan_lb<<<NB, 256>>>(deg, dinv, counts, offs, N, NB);
    fill_csr<<<(E + 255) / 256, 256>>>(row, col, ew, dinv, offs, rank, edges, E);

    // join x2h before gather1
    cudaStreamWaitEvent(0, evX, 0);
    gather1<<<(N + 7) / 8, 256>>>((const float4*)x, (const uint4*)xh, edges, offs, dinv,
                                  (uint4*)a1hi, (uint4*)a1lo, N);

    // join decompW before GEMM1
    cudaStreamWaitEvent(0, evW, 0);
    {
        dim3 grid(H1 / 128, M_PAD / 128);
        gemm_mma2<1, 4><<<grid, 256, SMEM_MI4>>>(a1hi, a1lo, w1thi, w1tlo,
                                                 f1hi, f1lo, H1, IN_DIM, b1, alpha);
    }
    {
        dim3 grid(H2 / 128, M_PAD / 64);
        gemm_mma2<0, 2><<<grid, 256, SMEM_MI2>>>(f1hi, f1lo, w2thi, w2tlo,
                                                 xw2h, nullptr, H2, H1, nullptr, nullptr);
    }

    gather2<<<(N + 7) / 8, 256>>>((const uint2*)xw2h, edges, offs, dinv,
                                  b2, alpha, (float4*)out, N);
}

// round 17
// speedup vs baseline: 1.1065x; 1.1065x over previous
#include <cuda_runtime.h>
#include <cuda_bf16.h>
#include <cuda_fp16.h>
#include <cstdint>

#define N_NODES 50000
#define N_EDGES 800000
#define IN_DIM  256
#define H1      512
#define H2      128
#define M_PAD   50048   // multiple of 128

// -------------------- scratch --------------------
__device__ float g_deg [N_NODES];
__device__ float g_dinv[N_NODES];
__device__ int   g_counts[N_NODES];
__device__ int   g_rank[N_EDGES];
__device__ int   g_offs [N_NODES + 1];
__device__ unsigned long long g_pkt[256];
__device__ unsigned int g_ticket;
__device__ int2  g_edge[N_EDGES];                     // packed (src, w-bits)
__device__ __half g_xh  [(size_t)N_NODES * IN_DIM];
__device__ __half g_xw2h[(size_t)M_PAD * H2];
__device__ __nv_bfloat16 g_a1hi[(size_t)M_PAD * IN_DIM];
__device__ __nv_bfloat16 g_a1lo[(size_t)M_PAD * IN_DIM];
__device__ __nv_bfloat16 g_f1hi[(size_t)M_PAD * H1];
__device__ __nv_bfloat16 g_f1lo[(size_t)M_PAD * H1];
__device__ __nv_bfloat16 g_w1thi[(size_t)H1 * IN_DIM];
__device__ __nv_bfloat16 g_w1tlo[(size_t)H1 * IN_DIM];
__device__ __nv_bfloat16 g_w2thi[(size_t)H2 * H1];
__device__ __nv_bfloat16 g_w2tlo[(size_t)H2 * H1];

// -------------------- helpers --------------------
__device__ __forceinline__ void mma_bf16(float* c, const uint32_t* a, const uint32_t* b) {
    asm volatile(
        "mma.sync.aligned.m16n8k16.row.col.f32.bf16.bf16.f32 "
        "{%0,%1,%2,%3}, {%4,%5,%6,%7}, {%8,%9}, {%0,%1,%2,%3};"
        : "+f"(c[0]), "+f"(c[1]), "+f"(c[2]), "+f"(c[3])
        : "r"(a[0]), "r"(a[1]), "r"(a[2]), "r"(a[3]), "r"(b[0]), "r"(b[1]));
}

__device__ __forceinline__ void ldsm4(uint32_t& r0, uint32_t& r1, uint32_t& r2,
                                      uint32_t& r3, uint32_t a) {
    asm volatile("ldmatrix.sync.aligned.m8n8.x4.shared.b16 {%0,%1,%2,%3}, [%4];"
                 : "=r"(r0), "=r"(r1), "=r"(r2), "=r"(r3) : "r"(a));
}

__device__ __forceinline__ void cp16(uint32_t saddr, const void* g) {
    asm volatile("cp.async.cg.shared.global [%0], [%1], 16;" :: "r"(saddr), "l"(g));
}
#define CP_COMMIT() asm volatile("cp.async.commit_group;" ::: "memory")
#define CP_WAIT(n)  asm volatile("cp.async.wait_group %0;" :: "n"(n) : "memory")

__device__ __forceinline__ uint32_t smem_u32(const void* p) {
    uint32_t a;
    asm("{ .reg .u64 t; cvta.to.shared.u64 t, %1; cvt.u32.u64 %0, t; }" : "=r"(a) : "l"(p));
    return a;
}

__device__ __forceinline__ void split4(float4 v, uint2& hi, uint2& lo) {
    __nv_bfloat16 h0 = __float2bfloat16(v.x), h1 = __float2bfloat16(v.y);
    __nv_bfloat16 h2 = __float2bfloat16(v.z), h3 = __float2bfloat16(v.w);
    __nv_bfloat162 hp0; hp0.x = h0; hp0.y = h1;
    __nv_bfloat162 hp1; hp1.x = h2; hp1.y = h3;
    __nv_bfloat162 lp0, lp1;
    lp0.x = __float2bfloat16(v.x - __bfloat162float(h0));
    lp0.y = __float2bfloat16(v.y - __bfloat162float(h1));
    lp1.x = __float2bfloat16(v.z - __bfloat162float(h2));
    lp1.y = __float2bfloat16(v.w - __bfloat162float(h3));
    hi = make_uint2(*(uint32_t*)&hp0, *(uint32_t*)&hp1);
    lo = make_uint2(*(uint32_t*)&lp0, *(uint32_t*)&lp1);
}

__device__ __forceinline__ void facc8(float* a, float w, uint4 u) {
    __half2 h0 = *(__half2*)&u.x, h1 = *(__half2*)&u.y;
    __half2 h2 = *(__half2*)&u.z, h3 = *(__half2*)&u.w;
    float2 f;
    f = __half22float2(h0); a[0] = fmaf(w, f.x, a[0]); a[1] = fmaf(w, f.y, a[1]);
    f = __half22float2(h1); a[2] = fmaf(w, f.x, a[2]); a[3] = fmaf(w, f.y, a[3]);
    f = __half22float2(h2); a[4] = fmaf(w, f.x, a[4]); a[5] = fmaf(w, f.y, a[5]);
    f = __half22float2(h3); a[6] = fmaf(w, f.x, a[6]); a[7] = fmaf(w, f.y, a[7]);
}

__device__ __forceinline__ float4 fma4h(float4 a, float w, uint2 u) {
    __half2 h0 = *(__half2*)&u.x, h1 = *(__half2*)&u.y;
    float2 f0 = __half22float2(h0), f1 = __half22float2(h1);
    a.x = fmaf(w, f0.x, a.x); a.y = fmaf(w, f0.y, a.y);
    a.z = fmaf(w, f1.x, a.z); a.w = fmaf(w, f1.y, a.w);
    return a;
}

// -------------------- CSR build --------------------
__global__ void init_all(float* deg, int* counts, int n) {
    int i = blockIdx.x * blockDim.x + threadIdx.x;
    if (i < n) { deg[i] = 1.0f; counts[i] = 0; }
    if (i < 256) g_pkt[i] = 0ull;
    if (i == 0) g_ticket = 0u;
}

__global__ void edge_accum(const int* __restrict__ col, const float* __restrict__ ew,
                           float* deg, int* counts, int* __restrict__ rank, int E) {
    int e = blockIdx.x * blockDim.x + threadIdx.x;
    if (e < E) {
        int c = col[e];
        atomicAdd(&deg[c], ew[e]);
        rank[e] = atomicAdd(&counts[c], 1);
    }
}

// fused: dinv = rsqrt(deg) + single-pass exclusive scan (warp-parallel lookback)
__global__ __launch_bounds__(256)
void rsqrt_scan_lb(const float* __restrict__ deg, float* __restrict__ dinv,
                   const int* __restrict__ counts, int* __restrict__ offs,
                   int n, int nb) {
    __shared__ int sh[256];
    __shared__ int bid_s, exc_s;
    const int t = threadIdx.x;
    if (t == 0) bid_s = (int)atomicAdd(&g_ticket, 1u);
    __syncthreads();
    const int bid = bid_s;
    const int gid = bid * 256 + t;

    if (gid < n) {
        float d = deg[gid];
        dinv[gid] = d > 0.f ? rsqrtf(d) : 0.f;
    }

    int v = (gid < n) ? counts[gid] : 0;
    sh[t] = v;
    __syncthreads();
#pragma unroll
    for (int d = 1; d < 256; d <<= 1) {
        int u = (t >= d) ? sh[t - d] : 0;
        __syncthreads();
        sh[t] += u;
        __syncthreads();
    }
    const int total = sh[255];

    if (t < 32) {
        if (bid == 0) {
            if (t == 0) {
                atomicExch(&g_pkt[0], (2ull << 32) | (unsigned)total);
                exc_s = 0;
            }
        } else {
            if (t == 0) atomicExch(&g_pkt[bid], (1ull << 32) | (unsigned)total);
            int exc = 0;
            int base_j = bid - 1;
            while (true) {
                int idx = base_j - t;
                unsigned long long p = 0;
                if (idx >= 0) {
                    do { p = atomicAdd(&g_pkt[idx], 0ull); } while ((p >> 32) == 0);
                }
                unsigned fm = __ballot_sync(0xffffffffu, idx >= 0 && (p >> 32) == 2ull);
                int tpre = __ffs(fm) - 1;
                unsigned contrib = (idx >= 0 && (tpre < 0 || t <= tpre)) ? (unsigned)p : 0u;
#pragma unroll
                for (int o = 16; o; o >>= 1) contrib += __shfl_xor_sync(0xffffffffu, contrib, o);
                exc += (int)contrib;
                if (tpre >= 0) break;
                base_j -= 32;
            }
            if (t == 0) {
                atomicExch(&g_pkt[bid], (2ull << 32) | (unsigned)(exc + total));
                exc_s = exc;
            }
        }
    }
    __syncthreads();
    const int base = exc_s;
    if (gid < n) offs[gid] = base + sh[t] - v;
    if (bid == nb - 1 && t == 255) offs[n] = base + total;
}

__global__ void fill_csr(const int* __restrict__ row, const int* __restrict__ col,
                         const float* __restrict__ ew, const float* __restrict__ dinv,
                         const int* __restrict__ offs, const int* __restrict__ rank,
                         int2* __restrict__ edges, int E) {
    int e = blockIdx.x * blockDim.x + threadIdx.x;
    if (e >= E) return;
    int r = row[e], c = col[e];
    int pos = offs[c] + rank[e];
    float w = dinv[r] * ew[e] * dinv[c];
    edges[pos] = make_int2(r, __float_as_int(w));
}

// x -> fp16
__global__ void x2h(const float4* __restrict__ x, uint2* __restrict__ xh, long n4) {
    long i = (long)blockIdx.x * blockDim.x + threadIdx.x;
    if (i >= n4) return;
    float4 v = x[i];
    __half2 p0 = __floats2half2_rn(v.x, v.y);
    __half2 p1 = __floats2half2_rn(v.z, v.w);
    xh[i] = make_uint2(*(uint32_t*)&p0, *(uint32_t*)&p1);
}

// both weight transposes + splits in one launch
__global__ void decompW(const float* __restrict__ W1, const float* __restrict__ W2,
                        __nv_bfloat16* __restrict__ w1hi, __nv_bfloat16* __restrict__ w1lo,
                        __nv_bfloat16* __restrict__ w2hi, __nv_bfloat16* __restrict__ w2lo) {
    const int n1 = IN_DIM * H1;
    const int n2 = H1 * H2;
    int i = blockIdx.x * blockDim.x + threadIdx.x;
    if (i < n1) {
        int k = i / H1, n = i % H1;
        float v = W1[i];
        __nv_bfloat16 h = __float2bfloat16(v);
        w1hi[(size_t)n * IN_DIM + k] = h;
        w1lo[(size_t)n * IN_DIM + k] = __float2bfloat16(v - __bfloat162float(h));
    } else if (i < n1 + n2) {
        int j = i - n1;
        int k = j / H2, n = j % H2;
        float v = W2[j];
        __nv_bfloat16 h = __float2bfloat16(v);
        w2hi[(size_t)n * H1 + k] = h;
        w2lo[(size_t)n * H1 + k] = __float2bfloat16(v - __bfloat162float(h));
    }
}

// -------------------- gather aggregations (warp per destination) ------------
__global__ __launch_bounds__(256)
void gather1(const float4* __restrict__ x, const uint4* __restrict__ xh,
             const int2* __restrict__ edges, const int* __restrict__ offs,
             const float* __restrict__ dinv,
             uint4* __restrict__ hi, uint4* __restrict__ lo, int n_nodes) {
    int node = blockIdx.x * 8 + (threadIdx.x >> 5);
    if (node >= n_nodes) return;
    const int lane = threadIdx.x & 31;
    const int s = offs[node], e = offs[node + 1];
    const float dv = dinv[node];
    const float sl = dv * dv;

    float a[8];
    {
        const float4* xr = x + (size_t)node * 64 + lane * 2;
        float4 v0 = __ldg(xr), v1 = __ldg(xr + 1);
        a[0] = sl * v0.x; a[1] = sl * v0.y; a[2] = sl * v0.z; a[3] = sl * v0.w;
        a[4] = sl * v1.x; a[5] = sl * v1.y; a[6] = sl * v1.z; a[7] = sl * v1.w;
    }

    int k = s;
    for (; k + 4 <= e; k += 4) {
        int2 e0 = __ldg(edges + k),     e1 = __ldg(edges + k + 1);
        int2 e2 = __ldg(edges + k + 2), e3 = __ldg(edges + k + 3);
        uint4 u0 = __ldg(xh + (size_t)e0.x * 32 + lane);
        uint4 u1 = __ldg(xh + (size_t)e1.x * 32 + lane);
        uint4 u2 = __ldg(xh + (size_t)e2.x * 32 + lane);
        uint4 u3 = __ldg(xh + (size_t)e3.x * 32 + lane);
        facc8(a, __int_as_float(e0.y), u0);
        facc8(a, __int_as_float(e1.y), u1);
        facc8(a, __int_as_float(e2.y), u2);
        facc8(a, __int_as_float(e3.y), u3);
    }
    for (; k < e; k++) {
        int2 e0 = __ldg(edges + k);
        facc8(a, __int_as_float(e0.y), __ldg(xh + (size_t)e0.x * 32 + lane));
    }

    uint2 h0, l0, h1, l1;
    split4(make_float4(a[0], a[1], a[2], a[3]), h0, l0);
    split4(make_float4(a[4], a[5], a[6], a[7]), h1, l1);
    hi[(size_t)node * 32 + lane] = make_uint4(h0.x, h0.y, h1.x, h1.y);
    lo[(size_t)node * 32 + lane] = make_uint4(l0.x, l0.y, l1.x, l1.y);
}

__global__ __launch_bounds__(256)
void gather2(const uint2* __restrict__ xwh, const int2* __restrict__ edges,
             const int* __restrict__ offs, const float* __restrict__ dinv,
             const float* __restrict__ b2, const float* __restrict__ alpha,
             float4* __restrict__ out, int n_nodes) {
    int node = blockIdx.x * 8 + (threadIdx.x >> 5);
    if (node >= n_nodes) return;
    const int lane = threadIdx.x & 31;
    const int s = offs[node], e = offs[node + 1];
    const float dv = dinv[node];
    const float sl = dv * dv;

    float4 a = make_float4(0.f, 0.f, 0.f, 0.f);
    a = fma4h(a, sl, __ldg(xwh + (size_t)node * 32 + lane));

    int k = s;
    for (; k + 8 <= e; k += 8) {
        int2 e0 = __ldg(edges + k),     e1 = __ldg(edges + k + 1);
        int2 e2 = __ldg(edges + k + 2), e3 = __ldg(edges + k + 3);
        int2 e4 = __ldg(edges + k + 4), e5 = __ldg(edges + k + 5);
        int2 e6 = __ldg(edges + k + 6), e7 = __ldg(edges + k + 7);
        uint2 u0 = __ldg(xwh + (size_t)e0.x * 32 + lane);
        uint2 u1 = __ldg(xwh + (size_t)e1.x * 32 + lane);
        uint2 u2 = __ldg(xwh + (size_t)e2.x * 32 + lane);
        uint2 u3 = __ldg(xwh + (size_t)e3.x * 32 + lane);
        uint2 u4 = __ldg(xwh + (size_t)e4.x * 32 + lane);
        uint2 u5 = __ldg(xwh + (size_t)e5.x * 32 + lane);
        uint2 u6 = __ldg(xwh + (size_t)e6.x * 32 + lane);
        uint2 u7 = __ldg(xwh + (size_t)e7.x * 32 + lane);
        a = fma4h(a, __int_as_float(e0.y), u0); a = fma4h(a, __int_as_float(e1.y), u1);
        a = fma4h(a, __int_as_float(e2.y), u2); a = fma4h(a, __int_as_float(e3.y), u3);
        a = fma4h(a, __int_as_float(e4.y), u4); a = fma4h(a, __int_as_float(e5.y), u5);
        a = fma4h(a, __int_as_float(e6.y), u6); a = fma4h(a, __int_as_float(e7.y), u7);
    }
    for (; k < e; k++) {
        int2 e0 = __ldg(edges + k);
        a = fma4h(a, __int_as_float(e0.y), __ldg(xwh + (size_t)e0.x * 32 + lane));
    }

    float4 bb = __ldg((const float4*)b2 + lane);
    float al = __ldg(alpha);
    a.x += bb.x; a.y += bb.y; a.z += bb.z; a.w += bb.w;
    a.x = a.x >= 0.f ? a.x : al * a.x;
    a.y = a.y >= 0.f ? a.y : al * a.y;
    a.z = a.z >= 0.f ? a.z : al * a.z;
    a.w = a.w >= 0.f ? a.w : al * a.w;
    out[(size_t)node * 32 + lane] = a;
}

// ---------- bf16x3 GEMM: HMMA + ldmatrix + 2-stage cp.async (2 CTAs/SM) ------
// OUT_MODE 0: fp16 C0. OUT_MODE 1: bias+PReLU, emit bf16 hi(C0)/lo(C1).
#define SPAD 40

template <int OUT_MODE, int MI>
__global__ __launch_bounds__(256)
void gemm_mma2(const __nv_bfloat16* __restrict__ Ahi, const __nv_bfloat16* __restrict__ Alo,
               const __nv_bfloat16* __restrict__ Bhi, const __nv_bfloat16* __restrict__ Blo,
               void* C0, void* C1, int Nc, int K,
               const float* __restrict__ bias, const float* __restrict__ alpha) {
    constexpr int BM = 32 * MI;
    constexpr int A_TILE = BM * SPAD;
    constexpr int B_TILE = 128 * SPAD;
    constexpr int STAGE  = 2 * A_TILE + 2 * B_TILE;

    extern __shared__ __nv_bfloat16 sm[];
    const uint32_t sbase = smem_u32(sm);

    const int tid  = threadIdx.x;
    const int wid  = tid >> 5;
    const int lane = tid & 31;
    const int wm   = wid >> 2;
    const int wn   = wid & 3;
    const int m0   = blockIdx.y * BM;
    const int n0   = blockIdx.x * 128;
    const int r4   = lane >> 2;
    const int t2   = (lane & 3) * 2;

    float acc[MI][4][4];
#pragma unroll
    for (int i = 0; i < MI; i++)
#pragma unroll
        for (int j = 0; j < 4; j++)
#pragma unroll
            for (int q = 0; q < 4; q++) acc[i][j][q] = 0.f;

    const int ldr = tid >> 2;
    const int ldq = tid & 3;
    const __nv_bfloat16* gAh = Ahi + (size_t)(m0 + ldr) * K + ldq * 8;
    const __nv_bfloat16* gAl = Alo + (size_t)(m0 + ldr) * K + ldq * 8;
    const __nv_bfloat16* gBh = Bhi + (size_t)(n0 + ldr) * K + ldq * 8;
    const __nv_bfloat16* gBl = Blo + (size_t)(n0 + ldr) * K + ldq * 8;

    auto tile_load = [&](int kc, int b) {
#pragma unroll
        for (int h = 0; h < MI / 2; h++) {
            uint32_t sa = sbase + (uint32_t)((b * STAGE + (ldr + h * 64) * SPAD + ldq * 8) * 2);
            cp16(sa, gAh + kc + (size_t)h * 64 * K);
            sa = sbase + (uint32_t)((b * STAGE + A_TILE + (ldr + h * 64) * SPAD + ldq * 8) * 2);
            cp16(sa, gAl + kc + (size_t)h * 64 * K);
        }
#pragma unroll
        for (int h = 0; h < 2; h++) {
            uint32_t sa = sbase + (uint32_t)((b * STAGE + 2 * A_TILE +
                              (ldr + h * 64) * SPAD + ldq * 8) * 2);
            cp16(sa, gBh + kc + (size_t)h * 64 * K);
            sa = sbase + (uint32_t)((b * STAGE + 2 * A_TILE + B_TILE +
                              (ldr + h * 64) * SPAD + ldq * 8) * 2);
            cp16(sa, gBl + kc + (size_t)h * 64 * K);
        }
    };

    const int arow = wm * (MI * 16) + (lane & 15);
    const int aoff = (lane >> 4) * 8;
    const int brow = wn * 32 + (lane & 7) + ((lane >> 4) & 1) * 8;
    const int boff = ((lane >> 3) & 1) * 8;

    tile_load(0, 0);
    CP_COMMIT();

    int buf = 0;
    for (int kc = 0; kc < K; kc += 32) {
        const bool more = (kc + 32) < K;
        if (more) {
            tile_load(kc + 32, buf ^ 1);
            CP_COMMIT();
            CP_WAIT(1);
        } else {
            CP_WAIT(0);
        }
        __syncthreads();

        const uint32_t aH = sbase + (uint32_t)((buf * STAGE) * 2);
        const uint32_t aL = aH + (uint32_t)(A_TILE * 2);
        const uint32_t bH = aH + (uint32_t)(2 * A_TILE * 2);
        const uint32_t bL = bH + (uint32_t)(B_TILE * 2);

#pragma unroll
        for (int kk = 0; kk < 32; kk += 16) {
            uint32_t bh[4][2], bl[4][2];
#pragma unroll
            for (int jp = 0; jp < 2; jp++) {
                uint32_t ad = bH + (uint32_t)(((brow + jp * 16) * SPAD + kk + boff) * 2);
                ldsm4(bh[2*jp][0], bh[2*jp][1], bh[2*jp+1][0], bh[2*jp+1][1], ad);
                ad = bL + (uint32_t)(((brow + jp * 16) * SPAD + kk + boff) * 2);
                ldsm4(bl[2*jp][0], bl[2*jp][1], bl[2*jp+1][0], bl[2*jp+1][1], ad);
            }
#pragma unroll
            for (int i = 0; i < MI; i++) {
                uint32_t ah[4], al[4];
                uint32_t ad = aH + (uint32_t)(((arow + i * 16) * SPAD + kk + aoff) * 2);
                ldsm4(ah[0], ah[1], ah[2], ah[3], ad);
                ad = aL + (uint32_t)(((arow + i * 16) * SPAD + kk + aoff) * 2);
                ldsm4(al[0], al[1], al[2], al[3], ad);
#pragma unroll
                for (int j = 0; j < 4; j++) {
                    mma_bf16(acc[i][j], ah, bh[j]);
                    mma_bf16(acc[i][j], ah, bl[j]);
                    mma_bf16(acc[i][j], al, bh[j]);
                }
            }
        }
        __syncthreads();
        buf ^= 1;
    }

    const float al_ = (OUT_MODE == 1) ? alpha[0] : 0.f;
#pragma unroll
    for (int i = 0; i < MI; i++) {
#pragma unroll
        for (int j = 0; j < 4; j++) {
            const int gm = m0 + wm * (MI * 16) + i * 16 + r4;
            const int gn = n0 + wn * 32 + j * 8 + t2;
            if (OUT_MODE == 0) {
                __half2 p0 = __floats2half2_rn(acc[i][j][0], acc[i][j][1]);
                __half2 p1 = __floats2half2_rn(acc[i][j][2], acc[i][j][3]);
                ((uint32_t*)C0)[((size_t)gm * Nc + gn) >> 1]       = *(uint32_t*)&p0;
                ((uint32_t*)C0)[((size_t)(gm + 8) * Nc + gn) >> 1] = *(uint32_t*)&p1;
            } else {
                const float bb0 = bias[gn], bb1 = bias[gn + 1];
#pragma unroll
                for (int h = 0; h < 2; h++) {
                    float v0 = acc[i][j][h * 2 + 0] + bb0;
                    float v1 = acc[i][j][h * 2 + 1] + bb1;
                    v0 = v0 >= 0.f ? v0 : al_ * v0;
                    v1 = v1 >= 0.f ? v1 : al_ * v1;
                    __nv_bfloat16 h0 = __float2bfloat16(v0), h1 = __float2bfloat16(v1);
                    __nv_bfloat162 hp; hp.x = h0; hp.y = h1;
                    __nv_bfloat162 lp;
                    lp.x = __float2bfloat16(v0 - __bfloat162float(h0));
                    lp.y = __float2bfloat16(v1 - __bfloat162float(h1));
                    const size_t go = ((size_t)(gm + h * 8) * Nc + gn) >> 1;
                    ((uint32_t*)C0)[go] = *(uint32_t*)&hp;
                    ((uint32_t*)C1)[go] = *(uint32_t*)&lp;
                }
            }
        }
    }
}

#define SMEM_MI4 ((2 * (2 * 128 * SPAD + 2 * 128 * SPAD)) * 2)   // 81920 B (2 CTAs/SM)
#define SMEM_MI2 ((2 * (2 * 64 * SPAD + 2 * 128 * SPAD)) * 2)    // 61440 B (3 CTAs/SM)

// -------------------- launch --------------------
extern "C" void kernel_launch(void* const* d_in, const int* in_sizes, int n_in,
                              void* d_out, int out_size) {
    const float* x     = (const float*)d_in[0];
    const float* ew    = (const float*)d_in[1];
    const float* W1    = (const float*)d_in[2];
    const float* b1    = (const float*)d_in[3];
    const float* W2    = (const float*)d_in[4];
    const float* b2    = (const float*)d_in[5];
    const float* alpha = (const float*)d_in[6];
    const int*   eidx  = (const int*)  d_in[7];

    const int E = in_sizes[1];
    const int N = in_sizes[0] / IN_DIM;
    const int* row = eidx;
    const int* col = eidx + E;
    float* out = (float*)d_out;

    float *deg, *dinv;
    int *counts, *rank, *offs;
    int2* edges;
    __half *xh, *xw2h;
    __nv_bfloat16 *a1hi, *a1lo, *f1hi, *f1lo, *w1thi, *w1tlo, *w2thi, *w2tlo;
    cudaGetSymbolAddress((void**)&deg,    g_deg);
    cudaGetSymbolAddress((void**)&dinv,   g_dinv);
    cudaGetSymbolAddress((void**)&counts, g_counts);
    cudaGetSymbolAddress((void**)&rank,   g_rank);
    cudaGetSymbolAddress((void**)&offs,   g_offs);
    cudaGetSymbolAddress((void**)&edges,  g_edge);
    cudaGetSymbolAddress((void**)&xh,     g_xh);
    cudaGetSymbolAddress((void**)&xw2h,   g_xw2h);
    cudaGetSymbolAddress((void**)&a1hi,   g_a1hi);
    cudaGetSymbolAddress((void**)&a1lo,   g_a1lo);
    cudaGetSymbolAddress((void**)&f1hi,   g_f1hi);
    cudaGetSymbolAddress((void**)&f1lo,   g_f1lo);
    cudaGetSymbolAddress((void**)&w1thi,  g_w1thi);
    cudaGetSymbolAddress((void**)&w1tlo,  g_w1tlo);
    cudaGetSymbolAddress((void**)&w2thi,  g_w2thi);
    cudaGetSymbolAddress((void**)&w2tlo,  g_w2tlo);

    static bool once = false;
    static cudaStream_t s1, s2;
    static cudaEvent_t evRoot, evX, evW;
    if (!once) {
        cudaFuncSetAttribute((const void*)gemm_mma2<1, 4>, cudaFuncAttributeMaxDynamicSharedMemorySize, SMEM_MI4);
        cudaFuncSetAttribute((const void*)gemm_mma2<0, 2>, cudaFuncAttributeMaxDynamicSharedMemorySize, SMEM_MI2);
        cudaStreamCreateWithFlags(&s1, cudaStreamNonBlocking);
        cudaStreamCreateWithFlags(&s2, cudaStreamNonBlocking);
        cudaEventCreateWithFlags(&evRoot, cudaEventDisableTiming);
        cudaEventCreateWithFlags(&evX,    cudaEventDisableTiming);
        cudaEventCreateWithFlags(&evW,    cudaEventDisableTiming);
        once = true;
    }

    const int NB = (N + 255) / 256;   // 196 (<= 256 lookback slots)

    // fork: prep work on side streams (overlaps the CSR chain)
    cudaEventRecord(evRoot, 0);
    cudaStreamWaitEvent(s1, evRoot, 0);
    cudaStreamWaitEvent(s2, evRoot, 0);
    x2h<<<(int)(((long)N * 64 + 255) / 256), 256, 0, s1>>>((const float4*)x, (uint2*)xh, (long)N * 64);
    cudaEventRecord(evX, s1);
    decompW<<<(IN_DIM * H1 + H1 * H2 + 255) / 256, 256, 0, s2>>>(W1, W2, w1thi, w1tlo, w2thi, w2tlo);
    cudaEventRecord(evW, s2);

    // main stream: CSR build
    init_all<<<NB, 256>>>(deg, counts, N);
    edge_accum<<<(E + 255) / 256, 256>>>(col, ew, deg, counts, rank, E);
    rsqrt_scan_lb<<<NB, 256>>>(deg, dinv, counts, offs, N, NB);
    fill_csr<<<(E + 255) / 256, 256>>>(row, col, ew, dinv, offs, rank, edges, E);

    // join x2h before gather1
    cudaStreamWaitEvent(0, evX, 0);
    gather1<<<(N + 7) / 8, 256>>>((const float4*)x, (const uint4*)xh, edges, offs, dinv,
                                  (uint4*)a1hi, (uint4*)a1lo, N);

    // join decompW before GEMM1
    cudaStreamWaitEvent(0, evW, 0);
    {
        dim3 grid(H1 / 128, M_PAD / 128);
        gemm_mma2<1, 4><<<grid, 256, SMEM_MI4>>>(a1hi, a1lo, w1thi, w1tlo,
                                                 f1hi, f1lo, H1, IN_DIM, b1, alpha);
    }
    {
        dim3 grid(H2 / 128, M_PAD / 64);
        gemm_mma2<0, 2><<<grid, 256, SMEM_MI2>>>(f1hi, f1lo, w2thi, w2tlo,
                                                 xw2h, nullptr, H2, H1, nullptr, nullptr);
    }

    gather2<<<(N + 7) / 8, 256>>>((const uint2*)xw2h, edges, offs, dinv,
                                  b2, alpha, (float4*)out, N);
}